// round 2
// baseline (speedup 1.0000x reference)
#include <cuda_runtime.h>
#include <math.h>
#include <stdint.h>

#define Nn 4096
#define Lt 256
#define TLt 128
#define MUc 0.001f
#define Ac 0.999f          /* 1-mu  */
#define OM2MU 0.998f       /* 1-2mu */
#define NM1 4095.0f
#define INV_NM1 (1.0f/4095.0f)
#define EPSF 2.2204460492503131e-16f

static const size_t NN = (size_t)Nn * (size_t)Nn;

// ---- scratch (device globals; no allocations allowed) ----
__device__ float g_Sfwd[(TLt + 1) * Nn];   // column sums per fwd step
__device__ float g_T[(Lt - TLt) * Nn];     // full column sums of beta per bwd step
__device__ float g_U[(Lt - TLt) * Nn];     // column sums of beta over rows with h_next==1
__device__ float g_Psum[Nn];
__device__ float g_rho[Lt];
__device__ float g_alpha_fb[(size_t)Nn * (size_t)Nn];  // fallback state if out buffer too small
__device__ float g_beta_fb[(size_t)Nn * (size_t)Nn];

// rho[l] = -expm1(-n_e * m[l]),  n_e = 4*10000/4096 = 9.765625
__global__ void k_rho(float* __restrict__ rho, const float* __restrict__ m) {
    int t = threadIdx.x;
    if (t < Lt) rho[t] = -expm1f(-9.765625f * m[t]);
}

// alpha0[i,j] = theta0[i,j] * pi[i,j];  accumulate S0[j] = colsum
__global__ void k_fwd_init(float* __restrict__ alpha, const int* __restrict__ h0,
                           float* __restrict__ S0) {
    const int j = (blockIdx.x << 10) + (threadIdx.x << 2);
    const int i0 = blockIdx.y << 6;
    const int4 hj = *(const int4*)(h0 + j);
    __shared__ int sh[64];
    if (threadIdx.x < 64) sh[threadIdx.x] = h0[i0 + threadIdx.x];
    __syncthreads();
    float sx = 0, sy = 0, sz = 0, sw = 0;
    float* base = alpha + (size_t)i0 * Nn + j;
#pragma unroll 4
    for (int rr = 0; rr < 64; ++rr) {
        const int hi = sh[rr];
        const int i = i0 + rr;
        float ox = ((hi == hj.x) ? Ac : MUc) * INV_NM1;
        float oy = ((hi == hj.y) ? Ac : MUc) * INV_NM1;
        float oz = ((hi == hj.z) ? Ac : MUc) * INV_NM1;
        float ow = ((hi == hj.w) ? Ac : MUc) * INV_NM1;
        if (i == j)     ox = 0.f;
        if (i == j + 1) oy = 0.f;
        if (i == j + 2) oz = 0.f;
        if (i == j + 3) ow = 0.f;
        float4 v = make_float4(ox, oy, oz, ow);
        *(float4*)base = v;
        base += Nn;
        sx += ox; sy += oy; sz += oz; sw += ow;
    }
    atomicAdd(S0 + j, sx);     atomicAdd(S0 + j + 1, sy);
    atomicAdd(S0 + j + 2, sz); atomicAdd(S0 + j + 3, sw);
}

// alpha[i,j] <- theta[i,j]*((1-r)*alpha[i,j]/S[j] + r/(n-1)),  diag->0; accumulate Snext
__global__ void k_fwd_step(float* __restrict__ alpha, const int* __restrict__ hrow,
                           const float* __restrict__ Sin, float* __restrict__ Sout,
                           const float* __restrict__ rho, int ridx) {
    const int j = (blockIdx.x << 10) + (threadIdx.x << 2);
    const int i0 = blockIdx.y << 6;
    const float r = __ldg(rho + ridx);
    const float omr = 1.0f - r;
    const float c = r * INV_NM1;
    const int4 hj = *(const int4*)(hrow + j);
    const float4 Sv = *(const float4*)(Sin + j);
    const float wx = omr / Sv.x, wy = omr / Sv.y, wz = omr / Sv.z, ww = omr / Sv.w;
    __shared__ int sh[64];
    if (threadIdx.x < 64) sh[threadIdx.x] = hrow[i0 + threadIdx.x];
    __syncthreads();
    float sx = 0, sy = 0, sz = 0, sw = 0;
    float* base = alpha + (size_t)i0 * Nn + j;
#pragma unroll 4
    for (int rr = 0; rr < 64; ++rr) {
        const int hi = sh[rr];
        const int i = i0 + rr;
        float4 v = *(float4*)base;
        float ox = ((hi == hj.x) ? Ac : MUc) * fmaf(v.x, wx, c);
        float oy = ((hi == hj.y) ? Ac : MUc) * fmaf(v.y, wy, c);
        float oz = ((hi == hj.z) ? Ac : MUc) * fmaf(v.z, wz, c);
        float ow = ((hi == hj.w) ? Ac : MUc) * fmaf(v.w, ww, c);
        if (i == j)     ox = 0.f;
        if (i == j + 1) oy = 0.f;
        if (i == j + 2) oz = 0.f;
        if (i == j + 3) ow = 0.f;
        v.x = ox; v.y = oy; v.z = oz; v.w = ow;
        *(float4*)base = v;
        base += Nn;
        sx += ox; sy += oy; sz += oz; sw += ow;
    }
    atomicAdd(Sout + j, sx);     atomicAdd(Sout + j + 1, sy);
    atomicAdd(Sout + j + 2, sz); atomicAdd(Sout + j + 3, sw);
}

// T0[j]=N, U0[j]=count(h_last==1)
__global__ void k_bwd_init(const int* __restrict__ hlast, float* __restrict__ T0,
                           float* __restrict__ U0) {
    __shared__ int red[256];
    int t = threadIdx.x;
    int c = 0;
    for (int i = t; i < Nn; i += 256) c += hlast[i];
    red[t] = c;
    __syncthreads();
    for (int s = 128; s > 0; s >>= 1) {
        if (t < s) red[t] += red[t + s];
        __syncthreads();
    }
    float c1 = (float)red[0];
    for (int i = t; i < Nn; i += 256) { T0[i] = (float)Nn; U0[i] = c1; }
}

// b = theta*beta; beta <- ((1-r)*b/denom[j] + r)*offdiag
// denom[j] = (mu*T[j] + (1-2mu)*(h_j ? U[j] : T[j]-U[j]) - (1-mu)*betaDiag)/(n-1)
// accumulate Tout[j]=colsum(beta_new), Uout[j]=colsum over rows with h_next==1
__global__ void k_bwd_step(float* __restrict__ beta, const int* __restrict__ hc,
                           const int* __restrict__ hn,
                           const float* __restrict__ Tin, const float* __restrict__ Uin,
                           float* __restrict__ Tout, float* __restrict__ Uout,
                           const float* __restrict__ rho, int ridx,
                           float betaDiag, int first) {
    const int j = (blockIdx.x << 10) + (threadIdx.x << 2);
    const int i0 = blockIdx.y << 6;
    const float r = __ldg(rho + ridx);
    const float omr = 1.0f - r;
    const int4 hj = *(const int4*)(hc + j);
    const float4 Tv = *(const float4*)(Tin + j);
    const float4 Uv = *(const float4*)(Uin + j);
    const float dC = Ac * betaDiag;
    const float dbx = MUc * Tv.x + OM2MU * (hj.x ? Uv.x : (Tv.x - Uv.x)) - dC;
    const float dby = MUc * Tv.y + OM2MU * (hj.y ? Uv.y : (Tv.y - Uv.y)) - dC;
    const float dbz = MUc * Tv.z + OM2MU * (hj.z ? Uv.z : (Tv.z - Uv.z)) - dC;
    const float dbw = MUc * Tv.w + OM2MU * (hj.w ? Uv.w : (Tv.w - Uv.w)) - dC;
    const float kx = omr * NM1 / dbx;
    const float ky = omr * NM1 / dby;
    const float kz = omr * NM1 / dbz;
    const float kw = omr * NM1 / dbw;
    __shared__ int shc[64], shn[64];
    if (threadIdx.x < 64) {
        shc[threadIdx.x] = hc[i0 + threadIdx.x];
        shn[threadIdx.x] = hn[i0 + threadIdx.x];
    }
    __syncthreads();
    float tx = 0, ty = 0, tz = 0, tw = 0;
    float ux = 0, uy = 0, uz = 0, uw = 0;
    float* base = beta + (size_t)i0 * Nn + j;
#pragma unroll 4
    for (int rr = 0; rr < 64; ++rr) {
        const int hi = shc[rr];
        const float fn = (float)shn[rr];
        const int i = i0 + rr;
        float4 v;
        if (first) { v.x = v.y = v.z = v.w = 1.0f; }
        else       { v = *(float4*)base; }
        float ox = fmaf(((hi == hj.x) ? Ac : MUc) * v.x, kx, r);
        float oy = fmaf(((hi == hj.y) ? Ac : MUc) * v.y, ky, r);
        float oz = fmaf(((hi == hj.z) ? Ac : MUc) * v.z, kz, r);
        float ow = fmaf(((hi == hj.w) ? Ac : MUc) * v.w, kw, r);
        if (i == j)     ox = 0.f;
        if (i == j + 1) oy = 0.f;
        if (i == j + 2) oz = 0.f;
        if (i == j + 3) ow = 0.f;
        v.x = ox; v.y = oy; v.z = oz; v.w = ow;
        *(float4*)base = v;
        base += Nn;
        tx += ox; ty += oy; tz += oz; tw += ow;
        ux += ox * fn; uy += oy * fn; uz += oz * fn; uw += ow * fn;
    }
    atomicAdd(Tout + j, tx);     atomicAdd(Tout + j + 1, ty);
    atomicAdd(Tout + j + 2, tz); atomicAdd(Tout + j + 3, tw);
    atomicAdd(Uout + j, ux);     atomicAdd(Uout + j + 1, uy);
    atomicAdd(Uout + j + 2, uz); atomicAdd(Uout + j + 3, uw);
}

// praw = clip01(alpha)*clip01(beta); accumulate column sums
__global__ void k_post1(const float* __restrict__ a, const float* __restrict__ b,
                        float* __restrict__ praw, float* __restrict__ Psum) {
    const int j = (blockIdx.x << 10) + (threadIdx.x << 2);
    const int i0 = blockIdx.y << 6;
    float sx = 0, sy = 0, sz = 0, sw = 0;
    size_t off = (size_t)i0 * Nn + j;
#pragma unroll 4
    for (int rr = 0; rr < 64; ++rr) {
        float4 av = *(const float4*)(a + off);
        float4 bv = *(const float4*)(b + off);
        float px = __saturatef(av.x) * __saturatef(bv.x);
        float py = __saturatef(av.y) * __saturatef(bv.y);
        float pz = __saturatef(av.z) * __saturatef(bv.z);
        float pw = __saturatef(av.w) * __saturatef(bv.w);
        float4 pv = make_float4(px, py, pz, pw);
        *(float4*)(praw + off) = pv;
        off += Nn;
        sx += px; sy += py; sz += pz; sw += pw;
    }
    atomicAdd(Psum + j, sx);     atomicAdd(Psum + j + 1, sy);
    atomicAdd(Psum + j + 2, sz); atomicAdd(Psum + j + 3, sw);
}

// normalize p in place; d = -0.5*(log pc + log pc^T)*offdiag via paired 32x32 tiles
__global__ void k_post2(float* __restrict__ p, const float* __restrict__ Psum,
                        float* __restrict__ dOut) {
    const int bi = blockIdx.y, bj = blockIdx.x;
    if (bj < bi) return;
    __shared__ float lA[32][33];
    __shared__ float lB[32][33];
    const int tx = threadIdx.x & 31;
    const int ty0 = threadIdx.x >> 5;  // 0..7
    const int colA = (bj << 5) + tx;
    const int colB = (bi << 5) + tx;
    const float invPA = 1.0f / __ldg(Psum + colA);
    const float invPB = 1.0f / __ldg(Psum + colB);
    const bool diagBlk = (bi == bj);
#pragma unroll
    for (int k2 = 0; k2 < 4; ++k2) {
        const int y = ty0 + (k2 << 3);
        const int iA = (bi << 5) + y;
        float pa = p[(size_t)iA * Nn + colA] * invPA;
        p[(size_t)iA * Nn + colA] = pa;
        lA[y][tx] = logf(fmaxf(pa, EPSF));
        if (!diagBlk) {
            const int iB = (bj << 5) + y;
            float pb = p[(size_t)iB * Nn + colB] * invPB;
            p[(size_t)iB * Nn + colB] = pb;
            lB[y][tx] = logf(fmaxf(pb, EPSF));
        }
    }
    __syncthreads();
    if (dOut == nullptr) return;
    float (*lBr)[33] = diagBlk ? lA : lB;
#pragma unroll
    for (int k2 = 0; k2 < 4; ++k2) {
        const int y = ty0 + (k2 << 3);
        const int iA = (bi << 5) + y;
        float dv = (iA == colA) ? 0.f : -0.5f * (lA[y][tx] + lBr[tx][y]);
        dOut[(size_t)iA * Nn + colA] = dv;
        if (!diagBlk) {
            const int iB = (bj << 5) + y;
            float dv2 = -0.5f * (lB[y][tx] + lA[tx][y]);
            dOut[(size_t)iB * Nn + colB] = dv2;
        }
    }
}

extern "C" void kernel_launch(void* const* d_in, const int* in_sizes, int n_in,
                              void* d_out, int out_size) {
    const int* h = (const int*)d_in[0];
    const float* m = (const float*)d_in[1];
    float* out = (float*)d_out;

    void* sym;
    float *Sfwd, *Tarr, *Uarr, *Psum, *rho, *afb, *bfb;
    cudaGetSymbolAddress(&sym, g_Sfwd);     Sfwd = (float*)sym;
    cudaGetSymbolAddress(&sym, g_T);        Tarr = (float*)sym;
    cudaGetSymbolAddress(&sym, g_U);        Uarr = (float*)sym;
    cudaGetSymbolAddress(&sym, g_Psum);     Psum = (float*)sym;
    cudaGetSymbolAddress(&sym, g_rho);      rho  = (float*)sym;
    cudaGetSymbolAddress(&sym, g_alpha_fb); afb  = (float*)sym;
    cudaGetSymbolAddress(&sym, g_beta_fb);  bfb  = (float*)sym;

    float *pOut, *dOut, *alphaPtr, *betaPtr;
    size_t osz = (size_t)out_size;
    if (osz >= 4 * NN) {
        pOut = out; dOut = out + NN; alphaPtr = out + 2 * NN; betaPtr = out + 3 * NN;
    } else if (osz >= 2 * NN) {
        pOut = out; dOut = out + NN; alphaPtr = afb; betaPtr = bfb;
    } else {
        pOut = out; dOut = nullptr; alphaPtr = afb; betaPtr = bfb;
    }

    cudaMemsetAsync(Sfwd, 0, sizeof(float) * (TLt + 1) * Nn);
    cudaMemsetAsync(Tarr, 0, sizeof(float) * (Lt - TLt) * Nn);
    cudaMemsetAsync(Uarr, 0, sizeof(float) * (Lt - TLt) * Nn);
    cudaMemsetAsync(Psum, 0, sizeof(float) * Nn);

    k_rho<<<1, 256>>>(rho, m);

    dim3 grid(4, 64);
    k_fwd_init<<<grid, 256>>>(alphaPtr, h, Sfwd);
    for (int t = 1; t <= TLt; ++t) {
        k_fwd_step<<<grid, 256>>>(alphaPtr, h + (size_t)t * Nn,
                                  Sfwd + (size_t)(t - 1) * Nn,
                                  Sfwd + (size_t)t * Nn, rho, t - 1);
    }

    k_bwd_init<<<1, 256>>>(h + (size_t)(Lt - 1) * Nn, Tarr, Uarr);
    for (int k = 0; k < Lt - 1 - TLt; ++k) {
        k_bwd_step<<<grid, 256>>>(betaPtr,
                                  h + (size_t)(Lt - 1 - k) * Nn,
                                  h + (size_t)(Lt - 2 - k) * Nn,
                                  Tarr + (size_t)k * Nn, Uarr + (size_t)k * Nn,
                                  Tarr + (size_t)(k + 1) * Nn, Uarr + (size_t)(k + 1) * Nn,
                                  rho, Lt - 2 - k,
                                  (k == 0) ? 1.0f : 0.0f, (k == 0) ? 1 : 0);
    }

    k_post1<<<grid, 256>>>(alphaPtr, betaPtr, pOut, Psum);
    dim3 g2(Nn / 32, Nn / 32);
    k_post2<<<g2, 256>>>(pOut, Psum, dOut);
}

// round 3
// speedup vs baseline: 1.8828x; 1.8828x over previous
#include <cuda_runtime.h>
#include <math.h>
#include <stdint.h>

#define Nn 4096
#define Lt 256
#define TLt 128
#define MUc 0.001f
#define Ac 0.999f          /* 1-mu */
#define NM1 4095.0f
#define INV_NM1 (1.0f/4095.0f)
#define EPSF 2.2204460492503131e-16f
#define NNsz ((size_t)Nn*(size_t)Nn)

// ---- scratch (device globals; no allocations allowed) ----
__device__ uint32_t g_pk[Lt * 128];     // h packed to bits: [L][128] words
__device__ float    g_rho[Lt];
__device__ float    g_alpha_fb[NNsz];   // fallbacks if out buffer too small
__device__ float    g_beta_fb[NNsz];

// rho[l] = -expm1(-n_e * m[l]),  n_e = 4*10000/4096 = 9.765625
__global__ void k_rho(float* __restrict__ rho, const float* __restrict__ m) {
    int t = threadIdx.x;
    if (t < Lt) rho[t] = -expm1f(-9.765625f * m[t]);
}

// pack h rows into bitmasks
__global__ void k_pack(const int* __restrict__ h, uint32_t* __restrict__ pk) {
    const int l = blockIdx.x;
    const int w = threadIdx.x;           // 0..127
    const int* row = h + (size_t)l * Nn + w * 32;
    uint32_t v = 0;
#pragma unroll
    for (int b = 0; b < 32; ++b) v |= ((uint32_t)(row[b] & 1)) << b;
    pk[l * 128 + w] = v;
}

// block-wide reduction of 4 per-thread partials; writes RECIPROCAL of each sum
// to sOut[0..3]. 512 threads = 16 warps.
__device__ __forceinline__ void blockReduceInv4(float s0, float s1, float s2, float s3,
                                                float4* swarp, float* sOut, int t) {
#pragma unroll
    for (int off = 16; off; off >>= 1) {
        s0 += __shfl_xor_sync(0xFFFFFFFFu, s0, off);
        s1 += __shfl_xor_sync(0xFFFFFFFFu, s1, off);
        s2 += __shfl_xor_sync(0xFFFFFFFFu, s2, off);
        s3 += __shfl_xor_sync(0xFFFFFFFFu, s3, off);
    }
    if ((t & 31) == 0) swarp[t >> 5] = make_float4(s0, s1, s2, s3);
    __syncthreads();
    if (t < 16) {
        float4 v = swarp[t];
#pragma unroll
        for (int off = 8; off; off >>= 1) {
            v.x += __shfl_xor_sync(0xFFFFu, v.x, off, 16);
            v.y += __shfl_xor_sync(0xFFFFu, v.y, off, 16);
            v.z += __shfl_xor_sync(0xFFFFu, v.z, off, 16);
            v.w += __shfl_xor_sync(0xFFFFu, v.w, off, 16);
        }
        if (t == 0) {
            sOut[0] = 1.0f / v.x; sOut[1] = 1.0f / v.y;
            sOut[2] = 1.0f / v.z; sOut[3] = 1.0f / v.w;
        }
    }
    __syncthreads();
}

// ---------------- forward: all 129 steps resident in registers ----------------
// block owns 4 columns (j0..j0+3), thread t owns rows [8t, 8t+8).
__global__ void __launch_bounds__(512, 2) k_fwd(float* __restrict__ alphaOut) {
    const int t = threadIdx.x;
    const int j0 = blockIdx.x << 2;
    const int r0 = t << 3;
    __shared__ float4 swarp[16];
    __shared__ float sInv[4];
    __shared__ float srho[Lt];
    if (t < Lt) srho[t] = g_rho[t];

    float st[8][4];
#pragma unroll
    for (int r = 0; r < 8; ++r)
#pragma unroll
        for (int c = 0; c < 4; ++c) st[r][c] = 0.0f;
    __syncthreads();

    const int wWord = r0 >> 5, wSh = r0 & 31;
    const int jWord = j0 >> 5, jSh = j0 & 31;

    for (int step = 0; step <= TLt; ++step) {
        const uint32_t* row = g_pk + step * 128;
        const uint32_t hb = (__ldg(row + wWord) >> wSh) & 0xFFu;
        const uint32_t hj = (__ldg(row + jWord) >> jSh) & 0xFu;

        float wv, cst;
        if (step == 0) { wv = 0.0f; cst = INV_NM1; }
        else { const float r = srho[step - 1]; wv = 1.0f - r; cst = r * INV_NM1; }

        float P0[4], Q0[4], P1[4], Q1[4], sm[4];
#pragma unroll
        for (int c = 0; c < 4; ++c) {
            const bool hjc = (hj >> c) & 1u;
            const float e0 = hjc ? MUc : Ac;   // theta when h_i = 0
            const float e1 = hjc ? Ac : MUc;   // theta when h_i = 1
            const float wc = (step == 0) ? 0.0f : (wv * sInv[c]);
            P0[c] = e0 * wc; Q0[c] = e0 * cst;
            P1[c] = e1 * wc; Q1[c] = e1 * cst;
            sm[c] = 0.0f;
        }
#pragma unroll
        for (int r = 0; r < 8; ++r) {
            const bool hi = (hb >> r) & 1u;
#pragma unroll
            for (int c = 0; c < 4; ++c) {
                const float a = st[r][c];
                const float o = hi ? fmaf(a, P1[c], Q1[c]) : fmaf(a, P0[c], Q0[c]);
                st[r][c] = o;
                sm[c] += o;
            }
        }
        // zero diagonal and exclude it from the column sum
#pragma unroll
        for (int c = 0; c < 4; ++c) {
            const int dj = j0 + c;
            if ((dj >> 3) == t) { sm[c] -= st[dj & 7][c]; st[dj & 7][c] = 0.0f; }
        }
        if (step < TLt)
            blockReduceInv4(sm[0], sm[1], sm[2], sm[3], swarp, sInv, t);
    }
#pragma unroll
    for (int r = 0; r < 8; ++r)
        *(float4*)(alphaOut + (size_t)(r0 + r) * Nn + j0) =
            make_float4(st[r][0], st[r][1], st[r][2], st[r][3]);
}

// ---------------- backward: 127 steps resident + fused posterior ----------------
__global__ void __launch_bounds__(512, 2) k_bwd(float* __restrict__ betaOut,
                                                float* __restrict__ pOut,
                                                const float* __restrict__ alphaIn) {
    const int t = threadIdx.x;
    const int j0 = blockIdx.x << 2;
    const int r0 = t << 3;
    __shared__ float4 swarp[16];
    __shared__ float sInv[4];
    __shared__ float srho[Lt];
    if (t < Lt) srho[t] = g_rho[t];

    float st[8][4];
#pragma unroll
    for (int r = 0; r < 8; ++r)
#pragma unroll
        for (int c = 0; c < 4; ++c) st[r][c] = 1.0f;
    __syncthreads();

    const int wWord = r0 >> 5, wSh = r0 & 31;
    const int jWord = j0 >> 5, jSh = j0 & 31;

    for (int k = 0; k < Lt - 1 - TLt; ++k) {
        const int lr = Lt - 1 - k;                 // h row index l+1
        const uint32_t* row = g_pk + lr * 128;
        const uint32_t hb = (__ldg(row + wWord) >> wSh) & 0xFFu;
        const uint32_t hj = (__ldg(row + jWord) >> jSh) & 0xFu;
        const float rr = srho[Lt - 2 - k];

        float E0[4], E1[4], sm[4];
#pragma unroll
        for (int c = 0; c < 4; ++c) {
            const bool hjc = (hj >> c) & 1u;
            E0[c] = hjc ? MUc : Ac;
            E1[c] = hjc ? Ac : MUc;
            sm[c] = 0.0f;
        }
        // phase A: b = theta * beta, accumulate column sums
#pragma unroll
        for (int r = 0; r < 8; ++r) {
            const bool hi = (hb >> r) & 1u;
#pragma unroll
            for (int c = 0; c < 4; ++c) {
                const float b = (hi ? E1[c] : E0[c]) * st[r][c];
                st[r][c] = b;
                sm[c] += b;
            }
        }
        // exclude diagonal from the pi-weighted sum
#pragma unroll
        for (int c = 0; c < 4; ++c) {
            const int dj = j0 + c;
            if ((dj >> 3) == t) sm[c] -= st[dj & 7][c];
        }
        blockReduceInv4(sm[0], sm[1], sm[2], sm[3], swarp, sInv, t);
        // phase B: beta = (1-r)*b/denom + r, denom = sum/(n-1); zero diagonal
        float kc[4];
#pragma unroll
        for (int c = 0; c < 4; ++c) kc[c] = (1.0f - rr) * NM1 * sInv[c];
#pragma unroll
        for (int r = 0; r < 8; ++r)
#pragma unroll
            for (int c = 0; c < 4; ++c)
                st[r][c] = fmaf(st[r][c], kc[c], rr);
#pragma unroll
        for (int c = 0; c < 4; ++c) {
            const int dj = j0 + c;
            if ((dj >> 3) == t) st[dj & 7][c] = 0.0f;
        }
    }

    // ---- fused posterior: p = clip(alpha)*clip(beta), column-normalized ----
    float psum[4] = {0.f, 0.f, 0.f, 0.f};
#pragma unroll
    for (int r = 0; r < 8; ++r) {
        const float4 av = __ldg((const float4*)(alphaIn + (size_t)(r0 + r) * Nn + j0));
        psum[0] += __saturatef(av.x) * __saturatef(st[r][0]);
        psum[1] += __saturatef(av.y) * __saturatef(st[r][1]);
        psum[2] += __saturatef(av.z) * __saturatef(st[r][2]);
        psum[3] += __saturatef(av.w) * __saturatef(st[r][3]);
    }
    blockReduceInv4(psum[0], psum[1], psum[2], psum[3], swarp, sInv, t);

#pragma unroll
    for (int r = 0; r < 8; ++r) {
        // write beta
        *(float4*)(betaOut + (size_t)(r0 + r) * Nn + j0) =
            make_float4(st[r][0], st[r][1], st[r][2], st[r][3]);
        // recompute and write normalized p (alpha re-read is L1-hot)
        const float4 av = __ldg((const float4*)(alphaIn + (size_t)(r0 + r) * Nn + j0));
        float4 pv;
        pv.x = __saturatef(av.x) * __saturatef(st[r][0]) * sInv[0];
        pv.y = __saturatef(av.y) * __saturatef(st[r][1]) * sInv[1];
        pv.z = __saturatef(av.z) * __saturatef(st[r][2]) * sInv[2];
        pv.w = __saturatef(av.w) * __saturatef(st[r][3]) * sInv[3];
        *(float4*)(pOut + (size_t)(r0 + r) * Nn + j0) = pv;
    }
}

// d = -0.5*(log pc + log pc^T)*offdiag, p already normalized; paired 32x32 tiles
__global__ void k_dist(const float* __restrict__ p, float* __restrict__ dOut) {
    const int bi = blockIdx.y, bj = blockIdx.x;
    if (bj < bi) return;
    __shared__ float lA[32][33];
    __shared__ float lB[32][33];
    const int tx = threadIdx.x & 31;
    const int ty0 = threadIdx.x >> 5;  // 0..7
    const int colA = (bj << 5) + tx;
    const int colB = (bi << 5) + tx;
    const bool diagBlk = (bi == bj);
#pragma unroll
    for (int k2 = 0; k2 < 4; ++k2) {
        const int y = ty0 + (k2 << 3);
        const int iA = (bi << 5) + y;
        lA[y][tx] = logf(fmaxf(p[(size_t)iA * Nn + colA], EPSF));
        if (!diagBlk) {
            const int iB = (bj << 5) + y;
            lB[y][tx] = logf(fmaxf(p[(size_t)iB * Nn + colB], EPSF));
        }
    }
    __syncthreads();
    float (*lBr)[33] = diagBlk ? lA : lB;
#pragma unroll
    for (int k2 = 0; k2 < 4; ++k2) {
        const int y = ty0 + (k2 << 3);
        const int iA = (bi << 5) + y;
        float dv = (iA == colA) ? 0.f : -0.5f * (lA[y][tx] + lBr[tx][y]);
        dOut[(size_t)iA * Nn + colA] = dv;
        if (!diagBlk) {
            const int iB = (bj << 5) + y;
            dOut[(size_t)iB * Nn + colB] = -0.5f * (lB[y][tx] + lA[tx][y]);
        }
    }
}

extern "C" void kernel_launch(void* const* d_in, const int* in_sizes, int n_in,
                              void* d_out, int out_size) {
    const int* h = (const int*)d_in[0];
    const float* m = (const float*)d_in[1];
    float* out = (float*)d_out;

    void* sym;
    uint32_t* pk; float *rho, *afb, *bfb;
    cudaGetSymbolAddress(&sym, g_pk);       pk  = (uint32_t*)sym;
    cudaGetSymbolAddress(&sym, g_rho);      rho = (float*)sym;
    cudaGetSymbolAddress(&sym, g_alpha_fb); afb = (float*)sym;
    cudaGetSymbolAddress(&sym, g_beta_fb);  bfb = (float*)sym;

    float *pOut, *dOut, *alphaPtr, *betaPtr;
    size_t osz = (size_t)out_size;
    if (osz >= 4 * NNsz) {
        pOut = out; dOut = out + NNsz; alphaPtr = out + 2 * NNsz; betaPtr = out + 3 * NNsz;
    } else if (osz >= 2 * NNsz) {
        pOut = out; dOut = out + NNsz; alphaPtr = afb; betaPtr = bfb;
    } else {
        pOut = out; dOut = nullptr; alphaPtr = afb; betaPtr = bfb;
    }

    k_rho<<<1, 256>>>(rho, m);
    k_pack<<<Lt, 128>>>(h, pk);
    k_fwd<<<Nn / 4, 512>>>(alphaPtr);
    k_bwd<<<Nn / 4, 512>>>(betaPtr, pOut, alphaPtr);
    if (dOut != nullptr) {
        dim3 g2(Nn / 32, Nn / 32);
        k_dist<<<g2, 256>>>(pOut, dOut);
    }
}

// round 4
// speedup vs baseline: 2.8615x; 1.5198x over previous
#include <cuda_runtime.h>
#include <math.h>
#include <stdint.h>

#define Nn 4096
#define Lt 256
#define TLt 128
#define MUc 0.001f
#define Ac 0.999f          /* 1-mu */
#define NM1 4095.0f
#define INV_NM1 (1.0f/4095.0f)
#define EPSF 2.2204460492503131e-16f
#define NNsz ((size_t)Nn*(size_t)Nn)

typedef unsigned long long ull;

// ---- scratch (device globals; no allocations allowed) ----
__device__ uint32_t g_pk[Lt * 128];     // h packed to bits: [L][128] words
__device__ float    g_rho[Lt];
__device__ float    g_alpha_fb[NNsz];   // fallbacks if out buffer too small
__device__ float    g_beta_fb[NNsz];

// ---- packed f32x2 helpers ----
__device__ __forceinline__ ull pk2(float lo, float hi) {
    ull r; asm("mov.b64 %0,{%1,%2};" : "=l"(r) : "f"(lo), "f"(hi)); return r;
}
__device__ __forceinline__ void up2(ull v, float& lo, float& hi) {
    asm("mov.b64 {%0,%1},%2;" : "=f"(lo), "=f"(hi) : "l"(v));
}
__device__ __forceinline__ ull ffma2(ull a, ull b, ull c) {
    ull d; asm("fma.rn.f32x2 %0,%1,%2,%3;" : "=l"(d) : "l"(a), "l"(b), "l"(c)); return d;
}
__device__ __forceinline__ ull fmul2(ull a, ull b) {
    ull d; asm("mul.rn.f32x2 %0,%1,%2;" : "=l"(d) : "l"(a), "l"(b)); return d;
}
__device__ __forceinline__ ull fadd2(ull a, ull b) {
    ull d; asm("add.rn.f32x2 %0,%1,%2;" : "=l"(d) : "l"(a), "l"(b)); return d;
}

// rho[l] = -expm1(-n_e * m[l]),  n_e = 4*10000/4096 = 9.765625
__global__ void k_rho(float* __restrict__ rho, const float* __restrict__ m) {
    int t = threadIdx.x;
    if (t < Lt) rho[t] = -expm1f(-9.765625f * m[t]);
}

// pack h rows into bitmasks
__global__ void k_pack(const int* __restrict__ h, uint32_t* __restrict__ pk) {
    const int l = blockIdx.x;
    const int w = threadIdx.x;           // 0..127
    const int* row = h + (size_t)l * Nn + w * 32;
    uint32_t v = 0;
#pragma unroll
    for (int b = 0; b < 32; ++b) v |= ((uint32_t)(row[b] & 1)) << b;
    pk[l * 128 + w] = v;
}

// block-wide reduce of 4 partials; write RECIPROCALS to sOut[0..3]; 512 thr = 16 warps
__device__ __forceinline__ void blockReduceInv4(float s0, float s1, float s2, float s3,
                                                float4* swarp, float* sOut, int t) {
#pragma unroll
    for (int off = 16; off; off >>= 1) {
        s0 += __shfl_xor_sync(0xFFFFFFFFu, s0, off);
        s1 += __shfl_xor_sync(0xFFFFFFFFu, s1, off);
        s2 += __shfl_xor_sync(0xFFFFFFFFu, s2, off);
        s3 += __shfl_xor_sync(0xFFFFFFFFu, s3, off);
    }
    if ((t & 31) == 0) swarp[t >> 5] = make_float4(s0, s1, s2, s3);
    __syncthreads();
    if (t < 16) {
        float4 v = swarp[t];
#pragma unroll
        for (int off = 8; off; off >>= 1) {
            v.x += __shfl_xor_sync(0xFFFFu, v.x, off, 16);
            v.y += __shfl_xor_sync(0xFFFFu, v.y, off, 16);
            v.z += __shfl_xor_sync(0xFFFFu, v.z, off, 16);
            v.w += __shfl_xor_sync(0xFFFFu, v.w, off, 16);
        }
        if (t == 0) {
            sOut[0] = 1.0f / v.x; sOut[1] = 1.0f / v.y;
            sOut[2] = 1.0f / v.z; sOut[3] = 1.0f / v.w;
        }
    }
    __syncthreads();
}

// diag fix (fwd): subtract diag values from packed sums AND zero state lanes.
// positions: (a0 lane lo), (a1 lane hi), (b2 lane lo), (b3 lane hi)
__device__ __forceinline__ void diag_fix_fwd(ull& a0, ull& a1, ull& b2, ull& b3,
                                             ull& s0, ull& s1) {
    float lo, hi, sl, sh;
    up2(s0, sl, sh);
    up2(a0, lo, hi); sl -= lo; a0 = pk2(0.f, hi);
    up2(a1, lo, hi); sh -= hi; a1 = pk2(lo, 0.f);
    s0 = pk2(sl, sh);
    up2(s1, sl, sh);
    up2(b2, lo, hi); sl -= lo; b2 = pk2(0.f, hi);
    up2(b3, lo, hi); sh -= hi; b3 = pk2(lo, 0.f);
    s1 = pk2(sl, sh);
}
// diag fix (bwd phase A): subtract only (state b kept for phase B)
__device__ __forceinline__ void diag_sub(const ull a0, const ull a1, const ull b2,
                                         const ull b3, ull& s0, ull& s1) {
    float lo, hi, sl, sh;
    up2(s0, sl, sh);
    up2(a0, lo, hi); sl -= lo;
    up2(a1, lo, hi); sh -= hi;
    s0 = pk2(sl, sh);
    up2(s1, sl, sh);
    up2(b2, lo, hi); sl -= lo;
    up2(b3, lo, hi); sh -= hi;
    s1 = pk2(sl, sh);
}
__device__ __forceinline__ void diag_zero(ull& a0, ull& a1, ull& b2, ull& b3) {
    a0 &= 0xFFFFFFFF00000000ull;  // zero lo lane
    a1 &= 0x00000000FFFFFFFFull;  // zero hi lane
    b2 &= 0xFFFFFFFF00000000ull;
    b3 &= 0x00000000FFFFFFFFull;
}

// ---------------- forward body: 129 steps resident in registers ----------------
__device__ __forceinline__ void fwd_body(float* __restrict__ alphaOut, int blk,
                                         float4* swarp, float* sInv, float* srho) {
    const int t = threadIdx.x;
    const int j0 = blk << 2;
    const int r0 = t << 3;
    if (t < Lt) srho[t] = g_rho[t];
    if (t < 4) sInv[t] = 0.0f;   // avoid NaN in step-0 (w = 0 * sInv)

    ull st[8][2];
#pragma unroll
    for (int r = 0; r < 8; ++r) { st[r][0] = 0ull; st[r][1] = 0ull; }
    __syncthreads();

    const int wWord = r0 >> 5, wSh = r0 & 31;
    const int jWord = j0 >> 5, jSh = j0 & 31;
    const bool isDiagT = (t == (j0 >> 3));
    const bool diagHi = (j0 & 7) != 0;   // diag rows 4..7 vs 0..3

    for (int step = 0; step <= TLt; ++step) {
        const uint32_t* row = g_pk + step * 128;
        const uint32_t hb = __ldg(row + wWord) >> wSh;
        const uint32_t hj = (__ldg(row + jWord) >> jSh) & 0xFu;

        float wv, cst;
        if (step == 0) { wv = 0.0f; cst = INV_NM1; }
        else { const float r = srho[step - 1]; wv = 1.0f - r; cst = r * INV_NM1; }

        const float e0a = (hj & 1u) ? MUc : Ac, e1a = (hj & 1u) ? Ac : MUc;
        const float e0b = (hj & 2u) ? MUc : Ac, e1b = (hj & 2u) ? Ac : MUc;
        const float e0c = (hj & 4u) ? MUc : Ac, e1c = (hj & 4u) ? Ac : MUc;
        const float e0d = (hj & 8u) ? MUc : Ac, e1d = (hj & 8u) ? Ac : MUc;
        const ull E0p0 = pk2(e0a, e0b), E1p0 = pk2(e1a, e1b);
        const ull E0p1 = pk2(e0c, e0d), E1p1 = pk2(e1c, e1d);
        const ull wp0 = pk2(wv * sInv[0], wv * sInv[1]);
        const ull wp1 = pk2(wv * sInv[2], wv * sInv[3]);
        const ull cstp = pk2(cst, cst);

        ull sm0 = 0ull, sm1 = 0ull;
#pragma unroll
        for (int r = 0; r < 8; ++r) {
            const bool hi = (hb >> r) & 1u;
            const ull ea = hi ? E1p0 : E0p0;
            const ull eb = hi ? E1p1 : E0p1;
            const ull o0 = fmul2(ffma2(st[r][0], wp0, cstp), ea);
            const ull o1 = fmul2(ffma2(st[r][1], wp1, cstp), eb);
            st[r][0] = o0; st[r][1] = o1;
            sm0 = fadd2(sm0, o0); sm1 = fadd2(sm1, o1);
        }
        if (isDiagT) {
            if (diagHi) diag_fix_fwd(st[4][0], st[5][0], st[6][1], st[7][1], sm0, sm1);
            else        diag_fix_fwd(st[0][0], st[1][0], st[2][1], st[3][1], sm0, sm1);
        }
        if (step < TLt) {
            float a0, a1, a2, a3;
            up2(sm0, a0, a1); up2(sm1, a2, a3);
            blockReduceInv4(a0, a1, a2, a3, swarp, sInv, t);
        }
    }
#pragma unroll
    for (int r = 0; r < 8; ++r) {
        float x, y, z, w;
        up2(st[r][0], x, y); up2(st[r][1], z, w);
        *(float4*)(alphaOut + (size_t)(r0 + r) * Nn + j0) = make_float4(x, y, z, w);
    }
}

// ---------------- backward body: 127 steps resident ----------------
__device__ __forceinline__ void bwd_body(float* __restrict__ betaOut, int blk,
                                         float4* swarp, float* sInv, float* srho) {
    const int t = threadIdx.x;
    const int j0 = blk << 2;
    const int r0 = t << 3;
    if (t < Lt) srho[t] = g_rho[t];

    ull st[8][2];
    const ull one2 = pk2(1.0f, 1.0f);
#pragma unroll
    for (int r = 0; r < 8; ++r) { st[r][0] = one2; st[r][1] = one2; }
    __syncthreads();

    const int wWord = r0 >> 5, wSh = r0 & 31;
    const int jWord = j0 >> 5, jSh = j0 & 31;
    const bool isDiagT = (t == (j0 >> 3));
    const bool diagHi = (j0 & 7) != 0;

    for (int k = 0; k < Lt - 1 - TLt; ++k) {
        const int lr = Lt - 1 - k;                 // h row index l+1
        const uint32_t* row = g_pk + lr * 128;
        const uint32_t hb = __ldg(row + wWord) >> wSh;
        const uint32_t hj = (__ldg(row + jWord) >> jSh) & 0xFu;
        const float rr = srho[Lt - 2 - k];

        const float e0a = (hj & 1u) ? MUc : Ac, e1a = (hj & 1u) ? Ac : MUc;
        const float e0b = (hj & 2u) ? MUc : Ac, e1b = (hj & 2u) ? Ac : MUc;
        const float e0c = (hj & 4u) ? MUc : Ac, e1c = (hj & 4u) ? Ac : MUc;
        const float e0d = (hj & 8u) ? MUc : Ac, e1d = (hj & 8u) ? Ac : MUc;
        const ull E0p0 = pk2(e0a, e0b), E1p0 = pk2(e1a, e1b);
        const ull E0p1 = pk2(e0c, e0d), E1p1 = pk2(e1c, e1d);

        // phase A: b = theta * beta, accumulate column sums
        ull sm0 = 0ull, sm1 = 0ull;
#pragma unroll
        for (int r = 0; r < 8; ++r) {
            const bool hi = (hb >> r) & 1u;
            const ull ea = hi ? E1p0 : E0p0;
            const ull eb = hi ? E1p1 : E0p1;
            const ull b0 = fmul2(st[r][0], ea);
            const ull b1 = fmul2(st[r][1], eb);
            st[r][0] = b0; st[r][1] = b1;
            sm0 = fadd2(sm0, b0); sm1 = fadd2(sm1, b1);
        }
        if (isDiagT) {
            if (diagHi) diag_sub(st[4][0], st[5][0], st[6][1], st[7][1], sm0, sm1);
            else        diag_sub(st[0][0], st[1][0], st[2][1], st[3][1], sm0, sm1);
        }
        {
            float a0, a1, a2, a3;
            up2(sm0, a0, a1); up2(sm1, a2, a3);
            blockReduceInv4(a0, a1, a2, a3, swarp, sInv, t);
        }
        // phase B: beta = (1-r)*b*(n-1)/sum + r; zero diagonal
        const float kscale = (1.0f - rr) * NM1;
        const ull kp0 = pk2(kscale * sInv[0], kscale * sInv[1]);
        const ull kp1 = pk2(kscale * sInv[2], kscale * sInv[3]);
        const ull rp = pk2(rr, rr);
#pragma unroll
        for (int r = 0; r < 8; ++r) {
            st[r][0] = ffma2(st[r][0], kp0, rp);
            st[r][1] = ffma2(st[r][1], kp1, rp);
        }
        if (isDiagT) {
            if (diagHi) diag_zero(st[4][0], st[5][0], st[6][1], st[7][1]);
            else        diag_zero(st[0][0], st[1][0], st[2][1], st[3][1]);
        }
    }
#pragma unroll
    for (int r = 0; r < 8; ++r) {
        float x, y, z, w;
        up2(st[r][0], x, y); up2(st[r][1], z, w);
        *(float4*)(betaOut + (size_t)(r0 + r) * Nn + j0) = make_float4(x, y, z, w);
    }
}

// merged: blocks [0,1024) run forward, [1024,2048) run backward
__global__ void __launch_bounds__(512, 2) k_main(float* __restrict__ alphaOut,
                                                 float* __restrict__ betaOut) {
    __shared__ float4 swarp[16];
    __shared__ float sInv[4];
    __shared__ float srho[Lt];
    if (blockIdx.x < 1024) fwd_body(alphaOut, blockIdx.x, swarp, sInv, srho);
    else                   bwd_body(betaOut, blockIdx.x - 1024, swarp, sInv, srho);
}

// posterior: p = clip01(alpha)*clip01(beta), column-normalized
__global__ void __launch_bounds__(512, 2) k_post(const float* __restrict__ a,
                                                 const float* __restrict__ b,
                                                 float* __restrict__ pOut) {
    __shared__ float4 swarp[16];
    __shared__ float sInv[4];
    const int t = threadIdx.x;
    const int j0 = blockIdx.x << 2;
    const int r0 = t << 3;
    float pr[8][4];
    float s0 = 0, s1 = 0, s2 = 0, s3 = 0;
#pragma unroll
    for (int r = 0; r < 8; ++r) {
        const size_t off = (size_t)(r0 + r) * Nn + j0;
        const float4 av = __ldg((const float4*)(a + off));
        const float4 bv = __ldg((const float4*)(b + off));
        pr[r][0] = __saturatef(av.x) * __saturatef(bv.x);
        pr[r][1] = __saturatef(av.y) * __saturatef(bv.y);
        pr[r][2] = __saturatef(av.z) * __saturatef(bv.z);
        pr[r][3] = __saturatef(av.w) * __saturatef(bv.w);
        s0 += pr[r][0]; s1 += pr[r][1]; s2 += pr[r][2]; s3 += pr[r][3];
    }
    blockReduceInv4(s0, s1, s2, s3, swarp, sInv, t);
    const float i0 = sInv[0], i1 = sInv[1], i2 = sInv[2], i3 = sInv[3];
#pragma unroll
    for (int r = 0; r < 8; ++r) {
        *(float4*)(pOut + (size_t)(r0 + r) * Nn + j0) =
            make_float4(pr[r][0] * i0, pr[r][1] * i1, pr[r][2] * i2, pr[r][3] * i3);
    }
}

// d = -0.5*(log pc + log pc^T)*offdiag; p already normalized; paired 32x32 tiles
__global__ void k_dist(const float* __restrict__ p, float* __restrict__ dOut) {
    const int bi = blockIdx.y, bj = blockIdx.x;
    if (bj < bi) return;
    __shared__ float lA[32][33];
    __shared__ float lB[32][33];
    const int tx = threadIdx.x & 31;
    const int ty0 = threadIdx.x >> 5;  // 0..7
    const int colA = (bj << 5) + tx;
    const int colB = (bi << 5) + tx;
    const bool diagBlk = (bi == bj);
#pragma unroll
    for (int k2 = 0; k2 < 4; ++k2) {
        const int y = ty0 + (k2 << 3);
        const int iA = (bi << 5) + y;
        lA[y][tx] = logf(fmaxf(p[(size_t)iA * Nn + colA], EPSF));
        if (!diagBlk) {
            const int iB = (bj << 5) + y;
            lB[y][tx] = logf(fmaxf(p[(size_t)iB * Nn + colB], EPSF));
        }
    }
    __syncthreads();
    float (*lBr)[33] = diagBlk ? lA : lB;
#pragma unroll
    for (int k2 = 0; k2 < 4; ++k2) {
        const int y = ty0 + (k2 << 3);
        const int iA = (bi << 5) + y;
        float dv = (iA == colA) ? 0.f : -0.5f * (lA[y][tx] + lBr[tx][y]);
        dOut[(size_t)iA * Nn + colA] = dv;
        if (!diagBlk) {
            const int iB = (bj << 5) + y;
            dOut[(size_t)iB * Nn + colB] = -0.5f * (lB[y][tx] + lA[tx][y]);
        }
    }
}

extern "C" void kernel_launch(void* const* d_in, const int* in_sizes, int n_in,
                              void* d_out, int out_size) {
    const int* h = (const int*)d_in[0];
    const float* m = (const float*)d_in[1];
    float* out = (float*)d_out;

    void* sym;
    uint32_t* pk; float *rho, *afb, *bfb;
    cudaGetSymbolAddress(&sym, g_pk);       pk  = (uint32_t*)sym;
    cudaGetSymbolAddress(&sym, g_rho);      rho = (float*)sym;
    cudaGetSymbolAddress(&sym, g_alpha_fb); afb = (float*)sym;
    cudaGetSymbolAddress(&sym, g_beta_fb);  bfb = (float*)sym;

    float *pOut, *dOut, *alphaPtr, *betaPtr;
    size_t osz = (size_t)out_size;
    if (osz >= 4 * NNsz) {
        pOut = out; dOut = out + NNsz; alphaPtr = out + 2 * NNsz; betaPtr = out + 3 * NNsz;
    } else if (osz >= 2 * NNsz) {
        pOut = out; dOut = out + NNsz; alphaPtr = afb; betaPtr = bfb;
    } else {
        pOut = out; dOut = nullptr; alphaPtr = afb; betaPtr = bfb;
    }

    k_rho<<<1, 256>>>(rho, m);
    k_pack<<<Lt, 128>>>(h, pk);
    k_main<<<2048, 512>>>(alphaPtr, betaPtr);
    k_post<<<Nn / 4, 512>>>(alphaPtr, betaPtr, pOut);
    if (dOut != nullptr) {
        dim3 g2(Nn / 32, Nn / 32);
        k_dist<<<g2, 256>>>(pOut, dOut);
    }
}